// round 4
// baseline (speedup 1.0000x reference)
#include <cuda_runtime.h>

// DrQ-v2 random-shift augmentation.
// x: [B=32, L=16, c=9, h=84, w=84] fp32  -> 4608 planes of 84x84
// shift: [512, 2] int32 (sx, sy) in [0, 8]
// out[n,c,i,j] = x[n,c, clamp(i + sy - 4, 0, 83), clamp(j + sx - 4, 0, 83)]
//
// Strategy: stage the whole plane in smem with aligned, fully-coalesced
// float4 loads (minimal L1tex wavefronts), then do the +/-4-column
// misaligned gather out of smem (cheap LDS), and write coalesced float4.

#define PADV 4
#define NC 9
#define HH 84
#define WW 84
#define WV (WW / 4)          // 21 float4 per row
#define NVEC (HH * WV)       // 1764 float4 per plane
#define NPLANES (512 * NC)   // 4608
#define TPB 256
#define KUNROLL 7            // 7 * 256 = 1792 >= 1764

__global__ __launch_bounds__(TPB) void drq_shift_kernel(
    const float* __restrict__ x,
    const int* __restrict__ shift,
    float* __restrict__ out)
{
    __shared__ float s[HH * WW];       // 28224 B

    const int p = blockIdx.x;          // plane index = n * 9 + c
    const int n = p / NC;              // image index
    const int dx = __ldg(&shift[2 * n]) - PADV;      // [-4, 4]
    const int dy = __ldg(&shift[2 * n + 1]) - PADV;  // [-4, 4]

    const float4* __restrict__ xin4 =
        reinterpret_cast<const float4*>(x + (size_t)p * (HH * WW));
    float* __restrict__ o = out + (size_t)p * (HH * WW);

    const int t = threadIdx.x;

    // ---- Phase 1: aligned, coalesced plane load into smem ----
    float4 ld[KUNROLL];
    #pragma unroll
    for (int k = 0; k < KUNROLL; k++) {
        int vec = t + k * TPB;
        if (vec >= NVEC) vec = NVEC - 1;   // safe dummy so loads stay unconditional
        ld[k] = __ldcs(&xin4[vec]);
    }
    #pragma unroll
    for (int k = 0; k < KUNROLL; k++) {
        const int vec = t + k * TPB;
        if (vec < NVEC) {
            reinterpret_cast<float4*>(s)[vec] = ld[k];
        }
    }

    __syncthreads();

    // ---- Phase 2: shifted/clamped gather from smem, coalesced stores ----
    #pragma unroll
    for (int k = 0; k < KUNROLL; k++) {
        const int vec = t + k * TPB;
        if (vec >= NVEC) break;            // uniform across block (NVEC%TPB tail only in last k)

        const int i  = vec / WV;
        const int jv = vec - i * WV;
        const int j0 = jv * 4;

        int si = i + dy;
        si = si < 0 ? 0 : (si > HH - 1 ? HH - 1 : si);
        const float* __restrict__ row = s + si * WW;

        int c0 = j0 + dx;
        int c1 = c0 + 1;
        int c2 = c0 + 2;
        int c3 = c0 + 3;
        c0 = c0 < 0 ? 0 : (c0 > WW - 1 ? WW - 1 : c0);
        c1 = c1 < 0 ? 0 : (c1 > WW - 1 ? WW - 1 : c1);
        c2 = c2 < 0 ? 0 : (c2 > WW - 1 ? WW - 1 : c2);
        c3 = c3 < 0 ? 0 : (c3 > WW - 1 ? WW - 1 : c3);

        float4 v;
        v.x = row[c0];
        v.y = row[c1];
        v.z = row[c2];
        v.w = row[c3];

        __stcs(reinterpret_cast<float4*>(o) + vec, v);
    }
}

extern "C" void kernel_launch(void* const* d_in, const int* in_sizes, int n_in,
                              void* d_out, int out_size)
{
    const float* x     = (const float*)d_in[0];
    const int*   shift = (const int*)d_in[1];
    float*       out   = (float*)d_out;

    drq_shift_kernel<<<NPLANES, TPB>>>(x, shift, out);
}

// round 5
// speedup vs baseline: 1.2953x; 1.2953x over previous
#include <cuda_runtime.h>

// DrQ-v2 random-shift augmentation.
// x: [B=32, L=16, c=9, h=84, w=84] fp32  -> 4608 planes of 84x84
// shift: [512, 2] int32 (sx, sy) in [0, 8]
// out[n,c,i,j] = x[n,c, clamp(i + sy - 4, 0, 83), clamp(j + sx - 4, 0, 83)]
//
// Strategy: after clamping, every output row is a +/-4-column rotate (with
// edge replication) of ONE source row. Assemble each output float4 from two
// ALIGNED float4 loads (lo/hi) + a uniform component rotate by (dx & 3) +
// edge-override selects. All global traffic is LDG.128 / STG.128 coalesced.

#define PADV 4
#define NC 9
#define HH 84
#define WW 84
#define WV (WW / 4)          // 21 float4 per row
#define NVEC (HH * WV)       // 1764 float4 per plane
#define NPLANES (512 * NC)   // 4608
#define TPB 256
#define KU 7                 // 7 * 256 = 1792 >= 1764

__global__ __launch_bounds__(TPB) void drq_shift_kernel(
    const float* __restrict__ x,
    const int* __restrict__ shift,
    float* __restrict__ out)
{
    const int p = blockIdx.x;          // plane index = n * 9 + c
    const int n = p / NC;              // image index
    const int dx = __ldg(&shift[2 * n]) - PADV;      // [-4, 4]
    const int dy = __ldg(&shift[2 * n + 1]) - PADV;  // [-4, 4]
    const int r  = dx & 3;             // uniform component rotate

    const float4* __restrict__ xin4 =
        reinterpret_cast<const float4*>(x + (size_t)p * (HH * WW));
    float4* __restrict__ o4 =
        reinterpret_cast<float4*>(out + (size_t)p * (HH * WW));

    const int t = threadIdx.x;

    float4 lo[KU], hi[KU];

    // ---- Phase 1: front-batched aligned vector loads ----
    #pragma unroll
    for (int k = 0; k < KU; k++) {
        int vec = t + k * TPB;
        if (vec >= NVEC) vec = NVEC - 1;   // safe dummy for tail lanes

        const int i  = vec / WV;
        const int jv = vec - i * WV;

        int si = i + dy;
        si = si < 0 ? 0 : (si > HH - 1 ? HH - 1 : si);

        const int base = 4 * jv + dx;                       // [-4, 84]
        int b0 = base;     b0 = b0 < 0 ? 0 : (b0 > 83 ? 83 : b0);
        int b3 = base + 3; b3 = b3 < 0 ? 0 : (b3 > 83 ? 83 : b3);

        const float4* __restrict__ rowv = xin4 + si * WV;
        lo[k] = __ldcs(&rowv[b0 >> 2]);
        hi[k] = __ldcs(&rowv[b3 >> 2]);
    }

    // ---- Phase 2: rotate-select + edge overrides, coalesced stores ----
    #pragma unroll
    for (int k = 0; k < KU; k++) {
        const int vec = t + k * TPB;
        if (vec < NVEC) {
            const int i    = vec / WV;
            const int jv   = vec - i * WV;
            const int base = 4 * jv + dx;

            const float4 L = lo[k];
            const float4 H = hi[k];

            // rotate by r (uniform across the whole block)
            float4 f;
            f.x = (r == 0) ? L.x : ((r == 1) ? L.y : ((r == 2) ? L.z : L.w));
            f.y = (r == 0) ? L.y : ((r == 1) ? L.z : ((r == 2) ? L.w : H.x));
            f.z = (r == 0) ? L.z : ((r == 1) ? L.w : ((r == 2) ? H.x : H.y));
            f.w = (r == 0) ? L.w : ((r == 1) ? H.x : ((r == 2) ? H.y : H.z));

            // edge replication: col<0 -> in[0] (=L.x, since b0 clamped to 0),
            //                   col>83 -> in[83] (=H.w, since b3 clamped to 83)
            f.x = (base     < 0) ? L.x : ((base     > 83) ? H.w : f.x);
            f.y = (base + 1 < 0) ? L.x : ((base + 1 > 83) ? H.w : f.y);
            f.z = (base + 2 < 0) ? L.x : ((base + 2 > 83) ? H.w : f.z);
            f.w = (base + 3 < 0) ? L.x : ((base + 3 > 83) ? H.w : f.w);

            __stcs(&o4[vec], f);
        }
    }
}

extern "C" void kernel_launch(void* const* d_in, const int* in_sizes, int n_in,
                              void* d_out, int out_size)
{
    const float* x     = (const float*)d_in[0];
    const int*   shift = (const int*)d_in[1];
    float*       out   = (float*)d_out;

    drq_shift_kernel<<<NPLANES, TPB>>>(x, shift, out);
}